// round 12
// baseline (speedup 1.0000x reference)
#include <cuda_runtime.h>
#include <cuda_fp16.h>
#include <cstdint>

// Problem constants: B=4, S=256, D_MODEL=2048, H=256, HEAD_DIM=8
#define DM     2048
#define MROWS  1024
#define NHEAD  256
#define HD     8
#define SCALE_LOG2E 0.5101594977970228f     // (1/sqrt(8)) * log2(e)

// ---- fp16 mma.sync GEMM tiling: 128x128 CTA tile, 2 CTAs/SM ----
#define BMT 128
#define BNT 128
#define BKT 32                  // k-halves per tile (2 x k16 mma steps)
#define STAGES 4
#define HSTRIDE 48              // smem row stride in halves (96B): frag bank = 24tg+2tr, conflict-free
#define TILE_H (128 * HSTRIDE)  // 6144 halves = 12288 B per operand per stage
#define SMEM_BYTES (STAGES * 2 * TILE_H * 2)   // 98304 B; x2 CTAs = 192 KB/SM

// ---- device scratch ----
__device__ __half g_xh[MROWS * DM];        // fp16 x  [m][k]
__device__ __half g_wh[4][DM * DM];        // fp16 W^T [n][k]: Wq,Wk,Wv,Wo
__device__ __half g_qh[MROWS * DM];        // fp16 q
__device__ __half g_kh[MROWS * DM];        // fp16 k
__device__ __half g_vh[MROWS * DM];        // fp16 v
__device__ __half g_ath[MROWS * DM];       // fp16 attention output [m][k]
__device__ float  g_p0[MROWS * DM];        // out-proj split-K partial 0
__device__ float  g_p1[MROWS * DM];        // out-proj split-K partial 1

// ---------------------------------------------------------------------------
// helpers
// ---------------------------------------------------------------------------
__device__ __forceinline__ uint32_t smem_u32(const void* p) {
    uint32_t a;
    asm("{ .reg .u64 t; cvta.to.shared.u64 t, %1; cvt.u32.u64 %0, t; }" : "=r"(a) : "l"(p));
    return a;
}
__device__ __forceinline__ float fast_ex2(float x) {
    float r;
    asm("ex2.approx.f32 %0, %1;" : "=f"(r) : "f"(x));
    return r;
}
__device__ __forceinline__ uint32_t packh2(float lo, float hi) {
    __half2 h = __floats2half2_rn(lo, hi);
    return *reinterpret_cast<uint32_t*>(&h);
}
__device__ __forceinline__ void cp_async16(uint32_t dst, const void* src) {
    asm volatile("cp.async.cg.shared.global [%0], [%1], 16;" :: "r"(dst), "l"(src));
}
#define CP_COMMIT() asm volatile("cp.async.commit_group;" ::: "memory")
#define CP_WAIT(n)  asm volatile("cp.async.wait_group %0;" :: "n"(n) : "memory")

// fp16 m16n8k8, f32 accumulate (attention scores)
__device__ __forceinline__ void mma_16808(float c[4], uint32_t a0, uint32_t a1, uint32_t b0) {
    asm volatile(
        "mma.sync.aligned.m16n8k8.row.col.f32.f16.f16.f32 "
        "{%0,%1,%2,%3}, {%4,%5}, {%6}, {%0,%1,%2,%3};"
        : "+f"(c[0]), "+f"(c[1]), "+f"(c[2]), "+f"(c[3])
        : "r"(a0), "r"(a1), "r"(b0));
}
// fp16 m16n8k16, f32 accumulate (GEMMs + attention PV)
__device__ __forceinline__ void mma_16816(float c[4],
                                          uint32_t a0, uint32_t a1, uint32_t a2, uint32_t a3,
                                          uint32_t b0, uint32_t b1) {
    asm volatile(
        "mma.sync.aligned.m16n8k16.row.col.f32.f16.f16.f32 "
        "{%0,%1,%2,%3}, {%4,%5,%6,%7}, {%8,%9}, {%0,%1,%2,%3};"
        : "+f"(c[0]), "+f"(c[1]), "+f"(c[2]), "+f"(c[3])
        : "r"(a0), "r"(a1), "r"(a2), "r"(a3), "r"(b0), "r"(b1));
}

// ---------------------------------------------------------------------------
// fp16 tensor-core GEMM: C[128,128] tile = A @ Bw^T (+ bias)
// A: fp16 [M][K] row-major. Bw: fp16 [N][K] row-major (pre-transposed W).
// 8 warps: 2(M) x 4(N), warp tile 64x32. Output f32 (split-K partials) or
// fp16 (q/k/v, bias fused). k-permutation: mma k-positions {2tr,2tr+1} <-
// data cols {4tr,4tr+1}; positions {2tr+8,2tr+9} <- cols {4tr+2,4tr+3}:
// one LDS.64 per row yields a full fragment pair.
// 4-stage cp.async pipeline, ONE __syncthreads per k-tile.
// ---------------------------------------------------------------------------
template <typename CT>
__device__ __forceinline__ void gemm_body(const __half* __restrict__ A,
                                          const __half* __restrict__ Bw,
                                          const float* __restrict__ bias,
                                          CT* __restrict__ C,
                                          int koff, int nkt)
{
    extern __shared__ __half smh[];
    __half* const Asm = smh;                          // [STAGES][TILE_H]
    __half* const Bsm = smh + STAGES * TILE_H;

    const int tid  = threadIdx.x;
    const int wid  = tid >> 5;
    const int lane = tid & 31;
    const int tg   = lane >> 2;      // 0..7
    const int tr   = lane & 3;       // 0..3
    const int m0   = (wid & 1) * 64;
    const int n0   = (wid >> 1) * 32;
    const int row0 = blockIdx.y * BMT;
    const int col0 = blockIdx.x * BNT;

    const __half* gA = A  + (size_t)row0 * DM + koff;
    const __half* gB = Bw + (size_t)col0 * DM + koff;

    float acc[4][4][4];
#pragma unroll
    for (int mt = 0; mt < 4; mt++)
#pragma unroll
        for (int nt = 0; nt < 4; nt++)
#pragma unroll
            for (int i = 0; i < 4; i++) acc[mt][nt][i] = 0.f;

    // Bijective chunk remap keeps 16B cp.async stores bank-conflict-free.
#define PREFETCH(kt, s)                                                            \
    do {                                                                           \
        __half* da = Asm + (s) * TILE_H;                                           \
        __half* db = Bsm + (s) * TILE_H;                                           \
        const __half* sa = gA + (kt) * BKT;                                        \
        const __half* sb = gB + (kt) * BKT;                                        \
        _Pragma("unroll")                                                          \
        for (int i = 0; i < 2; i++) {                                              \
            int c = tid + i * 256;                                                 \
            int r = ((c >> 1) & 3) | (((c >> 3) & 31) << 2);                       \
            int q = (c & 1) | (((c >> 8) & 1) << 1);                               \
            cp_async16(smem_u32(da + r * HSTRIDE + q * 8),                         \
                       sa + (size_t)r * DM + q * 8);                               \
        }                                                                          \
        _Pragma("unroll")                                                          \
        for (int i = 0; i < 2; i++) {                                              \
            int c = tid + i * 256;                                                 \
            int r = ((c >> 1) & 3) | (((c >> 3) & 31) << 2);                       \
            int q = (c & 1) | (((c >> 8) & 1) << 1);                               \
            cp_async16(smem_u32(db + r * HSTRIDE + q * 8),                         \
                       sb + (size_t)r * DM + q * 8);                               \
        }                                                                          \
    } while (0)

    PREFETCH(0, 0);
    CP_COMMIT();
    PREFETCH(1, 1);
    CP_COMMIT();
    PREFETCH(2, 2);
    CP_COMMIT();

    for (int kt = 0; kt < nkt; kt++) {
        CP_WAIT(STAGES - 2);          // stage kt resident
        __syncthreads();              // + all warps done with slot (kt-1)
        if (kt + 3 < nkt) PREFETCH(kt + 3, (kt + 3) % STAGES);
        CP_COMMIT();                  // always commit: keeps group count aligned

        const __half* a = Asm + (kt % STAGES) * TILE_H;
        const __half* b = Bsm + (kt % STAGES) * TILE_H;
#pragma unroll
        for (int ks = 0; ks < 2; ks++) {              // 2 x k16 per k-tile
            const int k0 = ks * 16;
            uint2 au[4][2];
            uint2 bu[4];
#pragma unroll
            for (int mt = 0; mt < 4; mt++) {
                const __half* ap = a + (m0 + mt * 16 + tg) * HSTRIDE + k0 + 4 * tr;
                au[mt][0] = *reinterpret_cast<const uint2*>(ap);               // row tg
                au[mt][1] = *reinterpret_cast<const uint2*>(ap + 8 * HSTRIDE); // row tg+8
            }
#pragma unroll
            for (int nt = 0; nt < 4; nt++) {
                const __half* bp = b + (n0 + nt * 8 + tg) * HSTRIDE + k0 + 4 * tr;
                bu[nt] = *reinterpret_cast<const uint2*>(bp);
            }
#pragma unroll
            for (int mt = 0; mt < 4; mt++)
#pragma unroll
                for (int nt = 0; nt < 4; nt++)
                    mma_16816(acc[mt][nt],
                              au[mt][0].x, au[mt][1].x, au[mt][0].y, au[mt][1].y,
                              bu[nt].x, bu[nt].y);
        }
    }

#pragma unroll
    for (int mt = 0; mt < 4; mt++) {
        const int r1 = row0 + m0 + mt * 16 + tg;
        const int r2 = r1 + 8;
#pragma unroll
        for (int nt = 0; nt < 4; nt++) {
            const int cb = col0 + n0 + nt * 8 + 2 * tr;
            float2 bv = {0.f, 0.f};
            if (bias) bv = *reinterpret_cast<const float2*>(bias + cb);
            if constexpr (sizeof(CT) == 2) {
                __half2 h1 = __floats2half2_rn(acc[mt][nt][0] + bv.x, acc[mt][nt][1] + bv.y);
                __half2 h2 = __floats2half2_rn(acc[mt][nt][2] + bv.x, acc[mt][nt][3] + bv.y);
                *reinterpret_cast<__half2*>((__half*)C + (size_t)r1 * DM + cb) = h1;
                *reinterpret_cast<__half2*>((__half*)C + (size_t)r2 * DM + cb) = h2;
            } else {
                float2 o1, o2;
                o1.x = acc[mt][nt][0] + bv.x; o1.y = acc[mt][nt][1] + bv.y;
                o2.x = acc[mt][nt][2] + bv.x; o2.y = acc[mt][nt][3] + bv.y;
                *reinterpret_cast<float2*>((float*)C + (size_t)r1 * DM + cb) = o1;
                *reinterpret_cast<float2*>((float*)C + (size_t)r2 * DM + cb) = o2;
            }
        }
    }
#undef PREFETCH
}

__global__ __launch_bounds__(256, 2)
void qkv_tc(const float* __restrict__ bq, const float* __restrict__ bk,
            const float* __restrict__ bv)
{
    const int z = blockIdx.z;
    const float* bias = (z == 0) ? bq : (z == 1) ? bk : bv;
    __half* C         = (z == 0) ? g_qh : (z == 1) ? g_kh : g_vh;
    gemm_body<__half>(g_xh, g_wh[z], bias, C, 0, DM / BKT);
}

// out projection split-K=2 into f32 partials; deterministic reduce adds bias.
__global__ __launch_bounds__(256, 2)
void out_tc_split()
{
    const int z = blockIdx.z;
    float* C = (z == 0) ? g_p0 : g_p1;
    gemm_body<float>(g_ath, g_wh[3], nullptr, C, z * (DM / 2), DM / (2 * BKT));
}

__global__ __launch_bounds__(256)
void reduce_out(const float* __restrict__ bo, float* __restrict__ out)
{
    const int i = blockIdx.x * blockDim.x + threadIdx.x;      // float4 index
    const float4 a = reinterpret_cast<const float4*>(g_p0)[i];
    const float4 b = reinterpret_cast<const float4*>(g_p1)[i];
    const float4 bv = reinterpret_cast<const float4*>(bo)[i & (DM / 4 - 1)];
    float4 o;
    o.x = a.x + b.x + bv.x; o.y = a.y + b.y + bv.y;
    o.z = a.z + b.z + bv.z; o.w = a.w + b.w + bv.w;
    reinterpret_cast<float4*>(out)[i] = o;
}

// ---------------------------------------------------------------------------
// prep: z<4 -> W[K][N] f32 -> g_wh[z][N][K] fp16 (transpose + rne convert)
//       z==4 -> x f32 -> g_xh fp16
// ---------------------------------------------------------------------------
__global__ __launch_bounds__(256)
void prep(const float* __restrict__ x,
          const float* __restrict__ W0, const float* __restrict__ W1,
          const float* __restrict__ W2, const float* __restrict__ W3)
{
    const int z = blockIdx.z;
    if (z == 4) {
        const int linear = blockIdx.y * 64 + blockIdx.x;      // 0..4095
        if (linear >= MROWS * DM / 1024) return;
        const int i0 = linear * 256 + threadIdx.x;            // float4 index
        float4 v = reinterpret_cast<const float4*>(x)[i0];
        __half2 h0 = __floats2half2_rn(v.x, v.y);
        __half2 h1 = __floats2half2_rn(v.z, v.w);
        uint2 o;
        o.x = *reinterpret_cast<uint32_t*>(&h0);
        o.y = *reinterpret_cast<uint32_t*>(&h1);
        reinterpret_cast<uint2*>(g_xh)[i0] = o;
        return;
    }
    __shared__ float tile[32][33];
    const float* W = (z == 0) ? W0 : (z == 1) ? W1 : (z == 2) ? W2 : W3;
    __half* T = g_wh[z];
    const int x0 = blockIdx.x * 32;     // N direction in W
    const int y0 = blockIdx.y * 32;     // K direction in W
    const int tx = threadIdx.x & 31;
    const int ty = threadIdx.x >> 5;    // 0..7
#pragma unroll
    for (int i = 0; i < 4; i++)
        tile[ty + i * 8][tx] = W[(size_t)(y0 + ty + i * 8) * DM + x0 + tx];
    __syncthreads();
#pragma unroll
    for (int i = 0; i < 4; i++)
        T[(size_t)(x0 + ty + i * 8) * DM + y0 + tx] = __float2half_rn(tile[tx][ty + i * 8]);
}

// ---------------------------------------------------------------------------
// fp16 tensor-core attention. One CTA per (b,s) position m.
// Phase rotation cancels analytically: logits = (q.k)/sqrt(8); attn_i is
// discarded, so phase_shift never reaches the output.
// Score mma m16n8k8.f16 output layout (row tg, cols 2tr/2tr+1) IS the
// A-fragment layout of the PV m16n8k16 mma -> exp results feed PV directly
// (identity k-mapping, just f32->f16x2 packs). No softmax max (logits O(+-5)).
// ---------------------------------------------------------------------------
__global__ __launch_bounds__(256)
void attn_tc()
{
    __shared__ __half QT[NHEAD][8];    // [head][d], 16B rows
    __shared__ __half KT[NHEAD][8];
    __shared__ __half VT[8][264];      // [d][head], stride 264 halves

    const int m    = blockIdx.x;
    const int t    = threadIdx.x;
    const int w    = t >> 5;
    const int lane = t & 31;
    const int tg   = lane >> 2;     // 0..7
    const int tr   = lane & 3;      // 0..3
    const int m0w  = w * 32;        // warp's 32 q-heads

    {
        uint4 qv = reinterpret_cast<const uint4*>(g_qh + (size_t)m * DM)[t];
        uint4 kv = reinterpret_cast<const uint4*>(g_kh + (size_t)m * DM)[t];
        uint4 vv = reinterpret_cast<const uint4*>(g_vh + (size_t)m * DM)[t];
        *reinterpret_cast<uint4*>(QT[t]) = qv;
        *reinterpret_cast<uint4*>(KT[t]) = kv;
        const __half* vh = reinterpret_cast<const __half*>(&vv);
#pragma unroll
        for (int d = 0; d < 8; d++) VT[d][t] = vh[d];
    }
    __syncthreads();

    // Q fragments (hoisted): m-tile0 rows (tg, tg+8), m-tile1 rows (+16, +24)
    uint32_t aq0[2], aq1[2];
    aq0[0] = *reinterpret_cast<const uint32_t*>(&QT[m0w + tg     ][2 * tr]);
    aq0[1] = *reinterpret_cast<const uint32_t*>(&QT[m0w + tg +  8][2 * tr]);
    aq1[0] = *reinterpret_cast<const uint32_t*>(&QT[m0w + tg + 16][2 * tr]);
    aq1[1] = *reinterpret_cast<const uint32_t*>(&QT[m0w + tg + 24][2 * tr]);

    float l[4] = {0.f, 0.f, 0.f, 0.f};          // rowsums: tg, tg+8, tg+16, tg+24
    float out0[4] = {0.f, 0.f, 0.f, 0.f};
    float out1[4] = {0.f, 0.f, 0.f, 0.f};

    for (int it = 0; it < 16; it++) {
        const int g0 = it * 16;
        // K fragments for the two 8-key score tiles
        uint32_t bkA = *reinterpret_cast<const uint32_t*>(&KT[g0 + tg    ][2 * tr]);
        uint32_t bkB = *reinterpret_cast<const uint32_t*>(&KT[g0 + 8 + tg][2 * tr]);

        float cA0[4] = {0.f, 0.f, 0.f, 0.f};
        float cA1[4] = {0.f, 0.f, 0.f, 0.f};
        float cB0[4] = {0.f, 0.f, 0.f, 0.f};
        float cB1[4] = {0.f, 0.f, 0.f, 0.f};
        mma_16808(cA0, aq0[0], aq0[1], bkA);
        mma_16808(cA1, aq1[0], aq1[1], bkA);
        mma_16808(cB0, aq0[0], aq0[1], bkB);
        mma_16808(cB1, aq1[0], aq1[1], bkB);

        float pA00 = fast_ex2(cA0[0] * SCALE_LOG2E), pA01 = fast_ex2(cA0[1] * SCALE_LOG2E);
        float pA02 = fast_ex2(cA0[2] * SCALE_LOG2E), pA03 = fast_ex2(cA0[3] * SCALE_LOG2E);
        float pB00 = fast_ex2(cB0[0] * SCALE_LOG2E), pB01 = fast_ex2(cB0[1] * SCALE_LOG2E);
        float pB02 = fast_ex2(cB0[2] * SCALE_LOG2E), pB03 = fast_ex2(cB0[3] * SCALE_LOG2E);
        float pA10 = fast_ex2(cA1[0] * SCALE_LOG2E), pA11 = fast_ex2(cA1[1] * SCALE_LOG2E);
        float pA12 = fast_ex2(cA1[2] * SCALE_LOG2E), pA13 = fast_ex2(cA1[3] * SCALE_LOG2E);
        float pB10 = fast_ex2(cB1[0] * SCALE_LOG2E), pB11 = fast_ex2(cB1[1] * SCALE_LOG2E);
        float pB12 = fast_ex2(cB1[2] * SCALE_LOG2E), pB13 = fast_ex2(cB1[3] * SCALE_LOG2E);

        l[0] += (pA00 + pA01) + (pB00 + pB01);
        l[1] += (pA02 + pA03) + (pB02 + pB03);
        l[2] += (pA10 + pA11) + (pB10 + pB11);
        l[3] += (pA12 + pA13) + (pB12 + pB13);

        // V fragments: VT[tg][g0+2tr] pair + VT[tg][g0+8+2tr] pair
        uint32_t bv0 = *reinterpret_cast<const uint32_t*>(&VT[tg][g0 + 2 * tr]);
        uint32_t bv1 = *reinterpret_cast<const uint32_t*>(&VT[tg][g0 + 8 + 2 * tr]);

        mma_16816(out0, packh2(pA00, pA01), packh2(pA02, pA03),
                        packh2(pB00, pB01), packh2(pB02, pB03), bv0, bv1);
        mma_16816(out1, packh2(pA10, pA11), packh2(pA12, pA13),
                        packh2(pB10, pB11), packh2(pB12, pB13), bv0, bv1);
    }

    // reduce rowsums across the 4 lanes sharing each row
#pragma unroll
    for (int i = 0; i < 4; i++) {
        l[i] += __shfl_xor_sync(0xFFFFFFFFu, l[i], 1);
        l[i] += __shfl_xor_sync(0xFFFFFFFFu, l[i], 2);
    }
    const float i0 = 1.f / l[0], i1 = 1.f / l[1], i2 = 1.f / l[2], i3 = 1.f / l[3];

    // write fp16: row r, cols (2tr, 2tr+1) -> g_ath[m*2048 + r*8 + 2tr]
    __half* base = g_ath + (size_t)m * DM + 2 * tr;
    __half2 h;
    h = __floats2half2_rn(out0[0] * i0, out0[1] * i0);
    *reinterpret_cast<__half2*>(base + (m0w + tg     ) * HD) = h;
    h = __floats2half2_rn(out0[2] * i1, out0[3] * i1);
    *reinterpret_cast<__half2*>(base + (m0w + tg +  8) * HD) = h;
    h = __floats2half2_rn(out1[0] * i2, out1[1] * i2);
    *reinterpret_cast<__half2*>(base + (m0w + tg + 16) * HD) = h;
    h = __floats2half2_rn(out1[2] * i3, out1[3] * i3);
    *reinterpret_cast<__half2*>(base + (m0w + tg + 24) * HD) = h;
}

// ---------------------------------------------------------------------------
// Launch
// ---------------------------------------------------------------------------
extern "C" void kernel_launch(void* const* d_in, const int* in_sizes, int n_in,
                              void* d_out, int out_size)
{
    const float* x  = (const float*)d_in[0];
    // d_in[1] = phase_shift: cancels analytically, unused.
    const float* Wq = (const float*)d_in[2];
    const float* bq = (const float*)d_in[3];
    const float* Wk = (const float*)d_in[4];
    const float* bk = (const float*)d_in[5];
    const float* Wv = (const float*)d_in[6];
    const float* bv = (const float*)d_in[7];
    const float* Wo = (const float*)d_in[8];
    const float* bo = (const float*)d_in[9];
    float* out = (float*)d_out;

    cudaFuncSetAttribute(qkv_tc, cudaFuncAttributeMaxDynamicSharedMemorySize, SMEM_BYTES);
    cudaFuncSetAttribute(out_tc_split, cudaFuncAttributeMaxDynamicSharedMemorySize, SMEM_BYTES);

    prep<<<dim3(64, 64, 5), 256>>>(x, Wq, Wk, Wv, Wo);   // z<4: W transpose; z=4: x convert

    dim3 qkv_grid(DM / BNT, MROWS / BMT, 3);             // (16, 8, 3) = 384 CTAs
    qkv_tc<<<qkv_grid, 256, SMEM_BYTES>>>(bq, bk, bv);

    attn_tc<<<MROWS, 256>>>();

    dim3 out_grid(DM / BNT, MROWS / BMT, 2);             // (16, 8, 2) = 256 CTAs
    out_tc_split<<<out_grid, 256, SMEM_BYTES>>>();

    reduce_out<<<(MROWS * DM / 4) / 256, 256>>>(bo, out);
}

// round 13
// speedup vs baseline: 1.5215x; 1.5215x over previous
#include <cuda_runtime.h>
#include <cuda_fp16.h>
#include <cstdint>

// Problem constants: B=4, S=256, D_MODEL=2048, H=256, HEAD_DIM=8
#define DM     2048
#define MROWS  1024
#define NHEAD  256
#define HD     8
#define SCALE_LOG2E 0.5101594977970228f     // (1/sqrt(8)) * log2(e)

// ---- fp16 mma.sync GEMM tiling: 128x128 CTA tile, 128 threads, 2 CTAs/SM ----
#define BMT 128
#define BNT 128
#define BKT 32                  // k-halves per tile (2 x k16 mma steps)
#define STAGES 4
#define HSTRIDE 48              // smem row stride in halves (96B): conflict-free frags + stores
#define TILE_H (128 * HSTRIDE)  // 6144 halves = 12288 B per operand per stage
#define SMEM_BYTES (STAGES * 2 * TILE_H * 2)   // 98304 B; x2 CTAs = 192 KB/SM
#define GTHREADS 128            // 4 warps: 2(M) x 2(N), warp tile 64x64

// ---- device scratch ----
__device__ __half g_xh[MROWS * DM];        // fp16 x  [m][k]
__device__ __half g_wh[4][DM * DM];        // fp16 W^T [n][k]: Wq,Wk,Wv,Wo
__device__ __half g_qh[MROWS * DM];        // fp16 q
__device__ __half g_kh[MROWS * DM];        // fp16 k
__device__ __half g_vh[MROWS * DM];        // fp16 v
__device__ __half g_ath[MROWS * DM];       // fp16 attention output [m][k]
__device__ float  g_p0[MROWS * DM];        // out-proj split-K partial 0
__device__ float  g_p1[MROWS * DM];        // out-proj split-K partial 1

// ---------------------------------------------------------------------------
// helpers
// ---------------------------------------------------------------------------
__device__ __forceinline__ uint32_t smem_u32(const void* p) {
    uint32_t a;
    asm("{ .reg .u64 t; cvta.to.shared.u64 t, %1; cvt.u32.u64 %0, t; }" : "=r"(a) : "l"(p));
    return a;
}
__device__ __forceinline__ float fast_ex2(float x) {
    float r;
    asm("ex2.approx.f32 %0, %1;" : "=f"(r) : "f"(x));
    return r;
}
__device__ __forceinline__ uint32_t packh2(float lo, float hi) {
    __half2 h = __floats2half2_rn(lo, hi);
    return *reinterpret_cast<uint32_t*>(&h);
}
__device__ __forceinline__ void cp_async16(uint32_t dst, const void* src) {
    asm volatile("cp.async.cg.shared.global [%0], [%1], 16;" :: "r"(dst), "l"(src));
}
#define CP_COMMIT() asm volatile("cp.async.commit_group;" ::: "memory")
#define CP_WAIT(n)  asm volatile("cp.async.wait_group %0;" :: "n"(n) : "memory")

// fp16 m16n8k8, f32 accumulate (attention scores)
__device__ __forceinline__ void mma_16808(float c[4], uint32_t a0, uint32_t a1, uint32_t b0) {
    asm volatile(
        "mma.sync.aligned.m16n8k8.row.col.f32.f16.f16.f32 "
        "{%0,%1,%2,%3}, {%4,%5}, {%6}, {%0,%1,%2,%3};"
        : "+f"(c[0]), "+f"(c[1]), "+f"(c[2]), "+f"(c[3])
        : "r"(a0), "r"(a1), "r"(b0));
}
// fp16 m16n8k16, f32 accumulate (GEMMs + attention PV)
__device__ __forceinline__ void mma_16816(float c[4],
                                          uint32_t a0, uint32_t a1, uint32_t a2, uint32_t a3,
                                          uint32_t b0, uint32_t b1) {
    asm volatile(
        "mma.sync.aligned.m16n8k16.row.col.f32.f16.f16.f32 "
        "{%0,%1,%2,%3}, {%4,%5,%6,%7}, {%8,%9}, {%0,%1,%2,%3};"
        : "+f"(c[0]), "+f"(c[1]), "+f"(c[2]), "+f"(c[3])
        : "r"(a0), "r"(a1), "r"(a2), "r"(a3), "r"(b0), "r"(b1));
}

// ---------------------------------------------------------------------------
// fp16 tensor-core GEMM: C[128,128] tile = A @ Bw^T (+ bias)
// A: fp16 [M][K] row-major. Bw: fp16 [N][K] row-major (pre-transposed W).
// 128 threads, 4 warps: 2(M) x 2(N), warp tile 64x64 (mt=4, nt=8).
// Reads per warp-ks: 2*mt + nt = 16 LDS.64 for 32 mmas -> 1.0 crossbar
// phase per mma (the smem crossbar is the binding resource at 64x32).
// k-permutation: mma k-positions {2tr,2tr+1} <- data cols {4tr,4tr+1};
// positions {2tr+8,2tr+9} <- cols {4tr+2,4tr+3}: one LDS.64 = full pair.
// 4-stage cp.async pipeline, ONE __syncthreads per k-tile.
// ---------------------------------------------------------------------------
template <typename CT>
__device__ __forceinline__ void gemm_body(const __half* __restrict__ A,
                                          const __half* __restrict__ Bw,
                                          const float* __restrict__ bias,
                                          CT* __restrict__ C,
                                          int koff, int nkt)
{
    extern __shared__ __half smh[];
    __half* const Asm = smh;                          // [STAGES][TILE_H]
    __half* const Bsm = smh + STAGES * TILE_H;

    const int tid  = threadIdx.x;
    const int wid  = tid >> 5;
    const int lane = tid & 31;
    const int tg   = lane >> 2;      // 0..7
    const int tr   = lane & 3;       // 0..3
    const int m0   = (wid & 1) * 64;
    const int n0   = (wid >> 1) * 64;
    const int row0 = blockIdx.y * BMT;
    const int col0 = blockIdx.x * BNT;

    const __half* gA = A  + (size_t)row0 * DM + koff;
    const __half* gB = Bw + (size_t)col0 * DM + koff;

    float acc[4][8][4];
#pragma unroll
    for (int mt = 0; mt < 4; mt++)
#pragma unroll
        for (int nt = 0; nt < 8; nt++)
#pragma unroll
            for (int i = 0; i < 4; i++) acc[mt][nt][i] = 0.f;

    // 512 16B chunks per operand per stage; 128 threads x 4 each.
    // Bijective remap (r from bits 2..1 | 7..3, q from bits 0,8) keeps the
    // 16B stores bank-conflict-free with HSTRIDE=48 (unit = 6r+q, distinct
    // mod 8 over each 8-lane phase).
#define PREFETCH(kt, s)                                                            \
    do {                                                                           \
        __half* da = Asm + (s) * TILE_H;                                           \
        __half* db = Bsm + (s) * TILE_H;                                           \
        const __half* sa = gA + (kt) * BKT;                                        \
        const __half* sb = gB + (kt) * BKT;                                        \
        _Pragma("unroll")                                                          \
        for (int i = 0; i < 4; i++) {                                              \
            int c = tid + i * GTHREADS;                                            \
            int r = ((c >> 1) & 3) | (((c >> 3) & 31) << 2);                       \
            int q = (c & 1) | (((c >> 8) & 1) << 1);                               \
            cp_async16(smem_u32(da + r * HSTRIDE + q * 8),                         \
                       sa + (size_t)r * DM + q * 8);                               \
        }                                                                          \
        _Pragma("unroll")                                                          \
        for (int i = 0; i < 4; i++) {                                              \
            int c = tid + i * GTHREADS;                                            \
            int r = ((c >> 1) & 3) | (((c >> 3) & 31) << 2);                       \
            int q = (c & 1) | (((c >> 8) & 1) << 1);                               \
            cp_async16(smem_u32(db + r * HSTRIDE + q * 8),                         \
                       sb + (size_t)r * DM + q * 8);                               \
        }                                                                          \
    } while (0)

    PREFETCH(0, 0);
    CP_COMMIT();
    PREFETCH(1, 1);
    CP_COMMIT();
    PREFETCH(2, 2);
    CP_COMMIT();

    for (int kt = 0; kt < nkt; kt++) {
        CP_WAIT(STAGES - 2);          // stage kt resident
        __syncthreads();              // + all warps done with slot (kt-1)
        if (kt + 3 < nkt) PREFETCH(kt + 3, (kt + 3) % STAGES);
        CP_COMMIT();                  // always commit: keeps group count aligned

        const __half* a = Asm + (kt % STAGES) * TILE_H;
        const __half* b = Bsm + (kt % STAGES) * TILE_H;
#pragma unroll
        for (int ks = 0; ks < 2; ks++) {              // 2 x k16 per k-tile
            const int k0 = ks * 16;
            uint2 au[4][2];
            uint2 bu[8];
#pragma unroll
            for (int mt = 0; mt < 4; mt++) {
                const __half* ap = a + (m0 + mt * 16 + tg) * HSTRIDE + k0 + 4 * tr;
                au[mt][0] = *reinterpret_cast<const uint2*>(ap);               // row tg
                au[mt][1] = *reinterpret_cast<const uint2*>(ap + 8 * HSTRIDE); // row tg+8
            }
#pragma unroll
            for (int nt = 0; nt < 8; nt++) {
                const __half* bp = b + (n0 + nt * 8 + tg) * HSTRIDE + k0 + 4 * tr;
                bu[nt] = *reinterpret_cast<const uint2*>(bp);
            }
#pragma unroll
            for (int mt = 0; mt < 4; mt++)
#pragma unroll
                for (int nt = 0; nt < 8; nt++)
                    mma_16816(acc[mt][nt],
                              au[mt][0].x, au[mt][1].x, au[mt][0].y, au[mt][1].y,
                              bu[nt].x, bu[nt].y);
        }
    }

#pragma unroll
    for (int mt = 0; mt < 4; mt++) {
        const int r1 = row0 + m0 + mt * 16 + tg;
        const int r2 = r1 + 8;
#pragma unroll
        for (int nt = 0; nt < 8; nt++) {
            const int cb = col0 + n0 + nt * 8 + 2 * tr;
            float2 bv = {0.f, 0.f};
            if (bias) bv = *reinterpret_cast<const float2*>(bias + cb);
            if constexpr (sizeof(CT) == 2) {
                __half2 h1 = __floats2half2_rn(acc[mt][nt][0] + bv.x, acc[mt][nt][1] + bv.y);
                __half2 h2 = __floats2half2_rn(acc[mt][nt][2] + bv.x, acc[mt][nt][3] + bv.y);
                *reinterpret_cast<__half2*>((__half*)C + (size_t)r1 * DM + cb) = h1;
                *reinterpret_cast<__half2*>((__half*)C + (size_t)r2 * DM + cb) = h2;
            } else {
                float2 o1, o2;
                o1.x = acc[mt][nt][0] + bv.x; o1.y = acc[mt][nt][1] + bv.y;
                o2.x = acc[mt][nt][2] + bv.x; o2.y = acc[mt][nt][3] + bv.y;
                *reinterpret_cast<float2*>((float*)C + (size_t)r1 * DM + cb) = o1;
                *reinterpret_cast<float2*>((float*)C + (size_t)r2 * DM + cb) = o2;
            }
        }
    }
#undef PREFETCH
}

__global__ __launch_bounds__(GTHREADS, 2)
void qkv_tc(const float* __restrict__ bq, const float* __restrict__ bk,
            const float* __restrict__ bv)
{
    const int z = blockIdx.z;
    const float* bias = (z == 0) ? bq : (z == 1) ? bk : bv;
    __half* C         = (z == 0) ? g_qh : (z == 1) ? g_kh : g_vh;
    gemm_body<__half>(g_xh, g_wh[z], bias, C, 0, DM / BKT);
}

// out projection split-K=2 into f32 partials; deterministic reduce adds bias.
__global__ __launch_bounds__(GTHREADS, 2)
void out_tc_split()
{
    const int z = blockIdx.z;
    float* C = (z == 0) ? g_p0 : g_p1;
    gemm_body<float>(g_ath, g_wh[3], nullptr, C, z * (DM / 2), DM / (2 * BKT));
}

__global__ __launch_bounds__(256)
void reduce_out(const float* __restrict__ bo, float* __restrict__ out)
{
    const int i = blockIdx.x * blockDim.x + threadIdx.x;      // float4 index
    const float4 a = reinterpret_cast<const float4*>(g_p0)[i];
    const float4 b = reinterpret_cast<const float4*>(g_p1)[i];
    const float4 bv = reinterpret_cast<const float4*>(bo)[i & (DM / 4 - 1)];
    float4 o;
    o.x = a.x + b.x + bv.x; o.y = a.y + b.y + bv.y;
    o.z = a.z + b.z + bv.z; o.w = a.w + b.w + bv.w;
    reinterpret_cast<float4*>(out)[i] = o;
}

// ---------------------------------------------------------------------------
// prep: z<4 -> W[K][N] f32 -> g_wh[z][N][K] fp16 (transpose + rne convert)
//       z==4 -> x f32 -> g_xh fp16
// ---------------------------------------------------------------------------
__global__ __launch_bounds__(256)
void prep(const float* __restrict__ x,
          const float* __restrict__ W0, const float* __restrict__ W1,
          const float* __restrict__ W2, const float* __restrict__ W3)
{
    const int z = blockIdx.z;
    if (z == 4) {
        const int linear = blockIdx.y * 64 + blockIdx.x;      // 0..4095
        if (linear >= MROWS * DM / 1024) return;
        const int i0 = linear * 256 + threadIdx.x;            // float4 index
        float4 v = reinterpret_cast<const float4*>(x)[i0];
        __half2 h0 = __floats2half2_rn(v.x, v.y);
        __half2 h1 = __floats2half2_rn(v.z, v.w);
        uint2 o;
        o.x = *reinterpret_cast<uint32_t*>(&h0);
        o.y = *reinterpret_cast<uint32_t*>(&h1);
        reinterpret_cast<uint2*>(g_xh)[i0] = o;
        return;
    }
    __shared__ float tile[32][33];
    const float* W = (z == 0) ? W0 : (z == 1) ? W1 : (z == 2) ? W2 : W3;
    __half* T = g_wh[z];
    const int x0 = blockIdx.x * 32;     // N direction in W
    const int y0 = blockIdx.y * 32;     // K direction in W
    const int tx = threadIdx.x & 31;
    const int ty = threadIdx.x >> 5;    // 0..7
#pragma unroll
    for (int i = 0; i < 4; i++)
        tile[ty + i * 8][tx] = W[(size_t)(y0 + ty + i * 8) * DM + x0 + tx];
    __syncthreads();
#pragma unroll
    for (int i = 0; i < 4; i++)
        T[(size_t)(x0 + ty + i * 8) * DM + y0 + tx] = __float2half_rn(tile[tx][ty + i * 8]);
}

// ---------------------------------------------------------------------------
// fp16 tensor-core attention. One CTA per (b,s) position m.
// Phase rotation cancels analytically: logits = (q.k)/sqrt(8); attn_i is
// discarded, so phase_shift never reaches the output.
// Score mma m16n8k8.f16 output layout (row tg, cols 2tr/2tr+1) IS the
// A-fragment layout of the PV m16n8k16 mma -> exp results feed PV directly
// (identity k-mapping, just f32->f16x2 packs). No softmax max (logits O(+-5)).
// ---------------------------------------------------------------------------
__global__ __launch_bounds__(256)
void attn_tc()
{
    __shared__ __half QT[NHEAD][8];    // [head][d], 16B rows
    __shared__ __half KT[NHEAD][8];
    __shared__ __half VT[8][264];      // [d][head], stride 264 halves

    const int m    = blockIdx.x;
    const int t    = threadIdx.x;
    const int w    = t >> 5;
    const int lane = t & 31;
    const int tg   = lane >> 2;     // 0..7
    const int tr   = lane & 3;      // 0..3
    const int m0w  = w * 32;        // warp's 32 q-heads

    {
        uint4 qv = reinterpret_cast<const uint4*>(g_qh + (size_t)m * DM)[t];
        uint4 kv = reinterpret_cast<const uint4*>(g_kh + (size_t)m * DM)[t];
        uint4 vv = reinterpret_cast<const uint4*>(g_vh + (size_t)m * DM)[t];
        *reinterpret_cast<uint4*>(QT[t]) = qv;
        *reinterpret_cast<uint4*>(KT[t]) = kv;
        const __half* vh = reinterpret_cast<const __half*>(&vv);
#pragma unroll
        for (int d = 0; d < 8; d++) VT[d][t] = vh[d];
    }
    __syncthreads();

    // Q fragments (hoisted): m-tile0 rows (tg, tg+8), m-tile1 rows (+16, +24)
    uint32_t aq0[2], aq1[2];
    aq0[0] = *reinterpret_cast<const uint32_t*>(&QT[m0w + tg     ][2 * tr]);
    aq0[1] = *reinterpret_cast<const uint32_t*>(&QT[m0w + tg +  8][2 * tr]);
    aq1[0] = *reinterpret_cast<const uint32_t*>(&QT[m0w + tg + 16][2 * tr]);
    aq1[1] = *reinterpret_cast<const uint32_t*>(&QT[m0w + tg + 24][2 * tr]);

    float l[4] = {0.f, 0.f, 0.f, 0.f};          // rowsums: tg, tg+8, tg+16, tg+24
    float out0[4] = {0.f, 0.f, 0.f, 0.f};
    float out1[4] = {0.f, 0.f, 0.f, 0.f};

    for (int it = 0; it < 16; it++) {
        const int g0 = it * 16;
        uint32_t bkA = *reinterpret_cast<const uint32_t*>(&KT[g0 + tg    ][2 * tr]);
        uint32_t bkB = *reinterpret_cast<const uint32_t*>(&KT[g0 + 8 + tg][2 * tr]);

        float cA0[4] = {0.f, 0.f, 0.f, 0.f};
        float cA1[4] = {0.f, 0.f, 0.f, 0.f};
        float cB0[4] = {0.f, 0.f, 0.f, 0.f};
        float cB1[4] = {0.f, 0.f, 0.f, 0.f};
        mma_16808(cA0, aq0[0], aq0[1], bkA);
        mma_16808(cA1, aq1[0], aq1[1], bkA);
        mma_16808(cB0, aq0[0], aq0[1], bkB);
        mma_16808(cB1, aq1[0], aq1[1], bkB);

        float pA00 = fast_ex2(cA0[0] * SCALE_LOG2E), pA01 = fast_ex2(cA0[1] * SCALE_LOG2E);
        float pA02 = fast_ex2(cA0[2] * SCALE_LOG2E), pA03 = fast_ex2(cA0[3] * SCALE_LOG2E);
        float pB00 = fast_ex2(cB0[0] * SCALE_LOG2E), pB01 = fast_ex2(cB0[1] * SCALE_LOG2E);
        float pB02 = fast_ex2(cB0[2] * SCALE_LOG2E), pB03 = fast_ex2(cB0[3] * SCALE_LOG2E);
        float pA10 = fast_ex2(cA1[0] * SCALE_LOG2E), pA11 = fast_ex2(cA1[1] * SCALE_LOG2E);
        float pA12 = fast_ex2(cA1[2] * SCALE_LOG2E), pA13 = fast_ex2(cA1[3] * SCALE_LOG2E);
        float pB10 = fast_ex2(cB1[0] * SCALE_LOG2E), pB11 = fast_ex2(cB1[1] * SCALE_LOG2E);
        float pB12 = fast_ex2(cB1[2] * SCALE_LOG2E), pB13 = fast_ex2(cB1[3] * SCALE_LOG2E);

        l[0] += (pA00 + pA01) + (pB00 + pB01);
        l[1] += (pA02 + pA03) + (pB02 + pB03);
        l[2] += (pA10 + pA11) + (pB10 + pB11);
        l[3] += (pA12 + pA13) + (pB12 + pB13);

        uint32_t bv0 = *reinterpret_cast<const uint32_t*>(&VT[tg][g0 + 2 * tr]);
        uint32_t bv1 = *reinterpret_cast<const uint32_t*>(&VT[tg][g0 + 8 + 2 * tr]);

        mma_16816(out0, packh2(pA00, pA01), packh2(pA02, pA03),
                        packh2(pB00, pB01), packh2(pB02, pB03), bv0, bv1);
        mma_16816(out1, packh2(pA10, pA11), packh2(pA12, pA13),
                        packh2(pB10, pB11), packh2(pB12, pB13), bv0, bv1);
    }

#pragma unroll
    for (int i = 0; i < 4; i++) {
        l[i] += __shfl_xor_sync(0xFFFFFFFFu, l[i], 1);
        l[i] += __shfl_xor_sync(0xFFFFFFFFu, l[i], 2);
    }
    const float i0 = 1.f / l[0], i1 = 1.f / l[1], i2 = 1.f / l[2], i3 = 1.f / l[3];

    __half* base = g_ath + (size_t)m * DM + 2 * tr;
    __half2 h;
    h = __floats2half2_rn(out0[0] * i0, out0[1] * i0);
    *reinterpret_cast<__half2*>(base + (m0w + tg     ) * HD) = h;
    h = __floats2half2_rn(out0[2] * i1, out0[3] * i1);
    *reinterpret_cast<__half2*>(base + (m0w + tg +  8) * HD) = h;
    h = __floats2half2_rn(out1[0] * i2, out1[1] * i2);
    *reinterpret_cast<__half2*>(base + (m0w + tg + 16) * HD) = h;
    h = __floats2half2_rn(out1[2] * i3, out1[3] * i3);
    *reinterpret_cast<__half2*>(base + (m0w + tg + 24) * HD) = h;
}

// ---------------------------------------------------------------------------
// Launch
// ---------------------------------------------------------------------------
extern "C" void kernel_launch(void* const* d_in, const int* in_sizes, int n_in,
                              void* d_out, int out_size)
{
    const float* x  = (const float*)d_in[0];
    // d_in[1] = phase_shift: cancels analytically, unused.
    const float* Wq = (const float*)d_in[2];
    const float* bq = (const float*)d_in[3];
    const float* Wk = (const float*)d_in[4];
    const float* bk = (const float*)d_in[5];
    const float* Wv = (const float*)d_in[6];
    const float* bv = (const float*)d_in[7];
    const float* Wo = (const float*)d_in[8];
    const float* bo = (const float*)d_in[9];
    float* out = (float*)d_out;

    cudaFuncSetAttribute(qkv_tc, cudaFuncAttributeMaxDynamicSharedMemorySize, SMEM_BYTES);
    cudaFuncSetAttribute(out_tc_split, cudaFuncAttributeMaxDynamicSharedMemorySize, SMEM_BYTES);

    prep<<<dim3(64, 64, 5), 256>>>(x, Wq, Wk, Wv, Wo);   // z<4: W transpose; z=4: x convert

    dim3 qkv_grid(DM / BNT, MROWS / BMT, 3);             // (16, 8, 3) = 384 CTAs
    qkv_tc<<<qkv_grid, GTHREADS, SMEM_BYTES>>>(bq, bk, bv);

    attn_tc<<<MROWS, 256>>>();

    dim3 out_grid(DM / BNT, MROWS / BMT, 2);             // (16, 8, 2) = 256 CTAs
    out_tc_split<<<out_grid, GTHREADS, SMEM_BYTES>>>();

    reduce_out<<<(MROWS * DM / 4) / 256, 256>>>(bo, out);
}